// round 9
// baseline (speedup 1.0000x reference)
#include <cuda_runtime.h>
#include <cuda_fp16.h>
#include <cstdint>

// QuantizedCodebook: inputs [32,4096,64] f32, codebook [1024,64] f32.
// Output (f32 concat): [ loss(1) | z_q(N*64) | indices-as-f32(N) ]
//
// R9: fp16 two-plane shared-B HMMA. x = xh + xl (fp16+residual); B = ch only.
// acc += xh*ch; acc += xl*ch  => dot ~= x*ch, err = x*cl bounded per-row by
// Cauchy-Schwarz ||x||*max||cl||  (max||cl|| computed exactly in prep).
// Top-3 + exact rescore inside margin; FULL exact rescan if certification
// fails (s3 inside window) => indices provably exact.

#define D 64
#define KCODES 1024
#define TPB 256
#define ROWS_PER_CTA 128
#define CHUNK_N 128
#define NCHUNKS (KCODES / CHUNK_N)       // 8
#define NK 4                              // K=64 -> 4 k16 steps
#define RSA 272                           // A row: 128 fp16 (hi|lo) + 16B pad
#define RSB 144                           // B row: 64 fp16 + 16B pad

// dynamic smem layout
#define SM_B0 0                           // 128*144 = 18432 (A-stage overlaps B0/B1)
#define SM_B1 18432
#define SM_CS 36864                       // csqr[1024]
#define SM_TS 40960                       // float top3 s [128][3]
#define SM_TI 42496                       // int   top3 i [128][3]
#define SMEM_TOTAL 44032

__device__ double g_loss_accum;
__device__ unsigned int g_ticket;
__device__ float g_maxcl2 = 0.0f;         // max_j ||c_j - fp16(c_j)||^2 (monotone)
__device__ float g_csqr[KCODES];
__device__ unsigned int g_cb16[KCODES * 32];   // per code: 64 fp16 = 32 u32

// ---------------- helpers ----------------
__device__ __forceinline__ uint32_t smem_u32(const void* p) {
    uint32_t a;
    asm("{ .reg .u64 t; cvta.to.shared.u64 t, %1; cvt.u32.u64 %0, t; }"
        : "=r"(a) : "l"(p));
    return a;
}
// pack two f32 -> f16x2, r.lo = a, r.hi = b
__device__ __forceinline__ uint32_t packh(float a, float b) {
    uint32_t r;
    asm("cvt.rn.f16x2.f32 %0, %1, %2;" : "=r"(r) : "f"(b), "f"(a));
    return r;
}
__device__ __forceinline__ float2 unph(uint32_t h) {
    __half2 hh = *reinterpret_cast<__half2*>(&h);
    return __half22float2(hh);
}
__device__ __forceinline__ void ldsm4(uint32_t& r0, uint32_t& r1,
                                      uint32_t& r2, uint32_t& r3, uint32_t a) {
    asm volatile("ldmatrix.sync.aligned.m8n8.x4.shared.b16 {%0,%1,%2,%3}, [%4];"
                 : "=r"(r0), "=r"(r1), "=r"(r2), "=r"(r3) : "r"(a));
}
__device__ __forceinline__ void mma16816(float& c0, float& c1, float& c2, float& c3,
                                         uint32_t a0, uint32_t a1, uint32_t a2,
                                         uint32_t a3, uint32_t b0, uint32_t b1) {
    asm("mma.sync.aligned.m16n8k16.row.col.f32.f16.f16.f32 "
        "{%0,%1,%2,%3}, {%4,%5,%6,%7}, {%8,%9}, {%0,%1,%2,%3};"
        : "+f"(c0), "+f"(c1), "+f"(c2), "+f"(c3)
        : "r"(a0), "r"(a1), "r"(a2), "r"(a3), "r"(b0), "r"(b1));
}
__device__ __forceinline__ void cpa16(uint32_t dst, const void* src) {
    asm volatile("cp.async.cg.shared.global [%0], [%1], 16;"
                 :: "r"(dst), "l"(src));
}
#define CP_COMMIT() asm volatile("cp.async.commit_group;" ::: "memory")
#define CP_WAIT0()  asm volatile("cp.async.wait_group 0;" ::: "memory")

__device__ __forceinline__ void ins3(float s, int idx,
                                     float& s1, int& i1, float& s2, int& i2,
                                     float& s3, int& i3) {
    if (s < s3) {
        if (s < s2) {
            if (s < s1) { s3 = s2; i3 = i2; s2 = s1; i2 = i1; s1 = s; i1 = idx; }
            else        { s3 = s2; i3 = i2; s2 = s;  i2 = idx; }
        } else { s3 = s; i3 = idx; }
    }
}

// ---------------- kernel 1: prep (fp16 codebook + norms + maxcl) ----------------
__global__ void vq_prep_kernel(const float* __restrict__ codebook) {
    int j = blockIdx.x * blockDim.x + threadIdx.x;
    if (j == 0) { g_loss_accum = 0.0; g_ticket = 0u; }
    if (j >= KCODES) return;
    const float4* c4 = (const float4*)(codebook + (size_t)j * D);
    unsigned int* q = g_cb16 + (size_t)j * 32;
    float s = 0.0f, cl2 = 0.0f;
    #pragma unroll
    for (int i = 0; i < 16; i++) {
        float4 v = c4[i];
        s += v.x * v.x + v.y * v.y + v.z * v.z + v.w * v.w;
        uint32_t h0 = packh(v.x, v.y), h1 = packh(v.z, v.w);
        float2 f0 = unph(h0), f1 = unph(h1);
        float r0 = v.x - f0.x, r1 = v.y - f0.y;
        float r2 = v.z - f1.x, r3 = v.w - f1.y;
        cl2 += r0 * r0 + r1 * r1 + r2 * r2 + r3 * r3;
        q[2 * i] = h0; q[2 * i + 1] = h1;
    }
    g_csqr[j] = s;
    atomicMax((int*)&g_maxcl2, __float_as_int(cl2));   // cl2 >= 0: int cmp == float cmp
}

__device__ __forceinline__ float exact_score(const float4* x4,
                                             const float* __restrict__ cb, int j) {
    const float4* c4 = (const float4*)(cb + (size_t)j * D);
    float dot = 0.0f;
    #pragma unroll
    for (int i = 0; i < 16; i++) {
        float4 a = x4[i], b = c4[i];
        dot += a.x * b.x + a.y * b.y + a.z * b.z + a.w * b.w;
    }
    return fmaf(-2.0f, dot, g_csqr[j]);
}

// ---------------- kernel 2: main ----------------
__global__ void __launch_bounds__(TPB, 2)
vq_main_kernel(const float* __restrict__ inp,
               const float* __restrict__ codebook,
               float* __restrict__ out, int n_rows) {
    extern __shared__ char dsm[];
    const uint32_t sbase = smem_u32(dsm);
    float* s_csqr = (float*)(dsm + SM_CS);
    float* s_ts = (float*)(dsm + SM_TS);
    int*   s_ti = (int*)(dsm + SM_TI);

    const int tid = threadIdx.x;
    const int l = tid & 31;
    const int w = tid >> 5;
    const int row0 = blockIdx.x * ROWS_PER_CTA;

    // ---- stage A [128 rows][hi(64) | lo(64)] fp16, stride 272 (overlaps B bufs) ----
    if (tid < ROWS_PER_CTA) {
        const float4* xr = (const float4*)(inp + (size_t)(row0 + tid) * D);
        uint32_t* arow = (uint32_t*)(dsm + tid * RSA);
        #pragma unroll
        for (int i = 0; i < 16; i++) {
            float4 v = xr[i];
            uint32_t h0 = packh(v.x, v.y), h1 = packh(v.z, v.w);
            float2 f0 = unph(h0), f1 = unph(h1);
            uint32_t l0 = packh(v.x - f0.x, v.y - f0.y);
            uint32_t l1 = packh(v.z - f1.x, v.w - f1.y);
            arow[2 * i] = h0;       arow[2 * i + 1] = h1;        // hi plane
            arow[32 + 2 * i] = l0;  arow[32 + 2 * i + 1] = l1;   // lo plane
        }
    }
    for (int g = tid; g < KCODES; g += TPB) s_csqr[g] = g_csqr[g];
    __syncthreads();

    // ---- preload A fragments (held all kernel): hi + lo planes, 4 k-steps ----
    uint32_t afh[NK][4], afl[NK][4];
    {
        uint32_t aoff = (uint32_t)((w * 16 + (l & 15)) * RSA + ((l & 16) ? 16 : 0));
        #pragma unroll
        for (int k = 0; k < NK; k++) {
            ldsm4(afh[k][0], afh[k][1], afh[k][2], afh[k][3], sbase + aoff + k * 32);
            ldsm4(afl[k][0], afl[k][1], afl[k][2], afl[k][3], sbase + aoff + 128 + k * 32);
        }
    }
    __syncthreads();   // all A reads done before B overwrites the region

    float sA1 = 3.4e38f, sA2 = 3.4e38f, sA3 = 3.4e38f;
    float sB1 = 3.4e38f, sB2 = 3.4e38f, sB3 = 3.4e38f;
    int iA1 = 0, iA2 = 0, iA3 = 0, iB1 = 0, iB2 = 0, iB3 = 0;

    const uint32_t boff = (uint32_t)(((l & 7) + ((l & 16) ? 8 : 0)) * RSB
                                     + ((l & 8) ? 16 : 0));
    const int q2 = 2 * (l & 3);
    const uint4* cb4 = (const uint4*)g_cb16;
    const uint32_t bb[2] = { sbase + SM_B0, sbase + SM_B1 };

    // prefetch chunk 0: 128 codes x 128 B = 1024 x 16B
    #pragma unroll
    for (int g = tid; g < CHUNK_N * 8; g += TPB) {
        int r = g >> 3, c = g & 7;
        cpa16(bb[0] + (uint32_t)(r * RSB + c * 16), cb4 + (size_t)r * 8 + c);
    }
    CP_COMMIT();

    for (int t = 0; t < NCHUNKS; t++) {
        CP_WAIT0();
        __syncthreads();
        if (t + 1 < NCHUNKS) {
            const uint4* src = cb4 + (size_t)(t + 1) * CHUNK_N * 8;
            uint32_t dstb = bb[(t + 1) & 1];
            #pragma unroll
            for (int g = tid; g < CHUNK_N * 8; g += TPB) {
                int r = g >> 3, c = g & 7;
                cpa16(dstb + (uint32_t)(r * RSB + c * 16), src + (size_t)r * 8 + c);
            }
            CP_COMMIT();
        }
        const uint32_t bch = bb[t & 1];

        #pragma unroll
        for (int pair = 0; pair < 4; pair++) {   // 32 codes per pair
            float a0 = 0.f, a1 = 0.f, a2 = 0.f, a3 = 0.f;
            float a4 = 0.f, a5 = 0.f, a6 = 0.f, a7 = 0.f;
            float a8 = 0.f, a9 = 0.f, a10 = 0.f, a11 = 0.f;
            float a12 = 0.f, a13 = 0.f, a14 = 0.f, a15 = 0.f;
            uint32_t b0base = bch + (uint32_t)((2 * pair) * 16 * RSB) + boff;
            uint32_t b1base = b0base + (uint32_t)(16 * RSB);
            #pragma unroll
            for (int k = 0; k < NK; k++) {
                uint32_t p0, p1, p2, p3, q0, q1, q2r, q3;
                ldsm4(p0, p1, p2, p3, b0base + k * 32);
                ldsm4(q0, q1, q2r, q3, b1base + k * 32);
                // hi plane then lo plane, same B fragments, same accumulators
                mma16816(a0, a1, a2, a3,   afh[k][0], afh[k][1], afh[k][2], afh[k][3], p0, p1);
                mma16816(a4, a5, a6, a7,   afh[k][0], afh[k][1], afh[k][2], afh[k][3], p2, p3);
                mma16816(a8, a9, a10, a11, afh[k][0], afh[k][1], afh[k][2], afh[k][3], q0, q1);
                mma16816(a12, a13, a14, a15, afh[k][0], afh[k][1], afh[k][2], afh[k][3], q2r, q3);
                mma16816(a0, a1, a2, a3,   afl[k][0], afl[k][1], afl[k][2], afl[k][3], p0, p1);
                mma16816(a4, a5, a6, a7,   afl[k][0], afl[k][1], afl[k][2], afl[k][3], p2, p3);
                mma16816(a8, a9, a10, a11, afl[k][0], afl[k][1], afl[k][2], afl[k][3], q0, q1);
                mma16816(a12, a13, a14, a15, afl[k][0], afl[k][1], afl[k][2], afl[k][3], q2r, q3);
            }
            int cbase = t * CHUNK_N;
            int n0 = pair * 32 + q2;
            int n1 = n0 + 16;
            float cs0 = s_csqr[cbase + n0], cs1 = s_csqr[cbase + n0 + 1];
            float cs2 = s_csqr[cbase + n0 + 8], cs3 = s_csqr[cbase + n0 + 9];
            float cs4 = s_csqr[cbase + n1], cs5 = s_csqr[cbase + n1 + 1];
            float cs6 = s_csqr[cbase + n1 + 8], cs7 = s_csqr[cbase + n1 + 9];

            float vA0 = fmaf(-2.f, a0, cs0),  vA1 = fmaf(-2.f, a1, cs1);
            float vA2 = fmaf(-2.f, a4, cs2),  vA3 = fmaf(-2.f, a5, cs3);
            float vA4 = fmaf(-2.f, a8, cs4),  vA5 = fmaf(-2.f, a9, cs5);
            float vA6 = fmaf(-2.f, a12, cs6), vA7 = fmaf(-2.f, a13, cs7);
            float vB0 = fmaf(-2.f, a2, cs0),  vB1 = fmaf(-2.f, a3, cs1);
            float vB2 = fmaf(-2.f, a6, cs2),  vB3 = fmaf(-2.f, a7, cs3);
            float vB4 = fmaf(-2.f, a10, cs4), vB5 = fmaf(-2.f, a11, cs5);
            float vB6 = fmaf(-2.f, a14, cs6), vB7 = fmaf(-2.f, a15, cs7);

            float mA = fminf(fminf(fminf(vA0, vA1), fminf(vA2, vA3)),
                             fminf(fminf(vA4, vA5), fminf(vA6, vA7)));
            float mB = fminf(fminf(fminf(vB0, vB1), fminf(vB2, vB3)),
                             fminf(fminf(vB4, vB5), fminf(vB6, vB7)));
            if (mA < sA3) {
                ins3(vA0, cbase + n0,     sA1, iA1, sA2, iA2, sA3, iA3);
                ins3(vA1, cbase + n0 + 1, sA1, iA1, sA2, iA2, sA3, iA3);
                ins3(vA2, cbase + n0 + 8, sA1, iA1, sA2, iA2, sA3, iA3);
                ins3(vA3, cbase + n0 + 9, sA1, iA1, sA2, iA2, sA3, iA3);
                ins3(vA4, cbase + n1,     sA1, iA1, sA2, iA2, sA3, iA3);
                ins3(vA5, cbase + n1 + 1, sA1, iA1, sA2, iA2, sA3, iA3);
                ins3(vA6, cbase + n1 + 8, sA1, iA1, sA2, iA2, sA3, iA3);
                ins3(vA7, cbase + n1 + 9, sA1, iA1, sA2, iA2, sA3, iA3);
            }
            if (mB < sB3) {
                ins3(vB0, cbase + n0,     sB1, iB1, sB2, iB2, sB3, iB3);
                ins3(vB1, cbase + n0 + 1, sB1, iB1, sB2, iB2, sB3, iB3);
                ins3(vB2, cbase + n0 + 8, sB1, iB1, sB2, iB2, sB3, iB3);
                ins3(vB3, cbase + n0 + 9, sB1, iB1, sB2, iB2, sB3, iB3);
                ins3(vB4, cbase + n1,     sB1, iB1, sB2, iB2, sB3, iB3);
                ins3(vB5, cbase + n1 + 1, sB1, iB1, sB2, iB2, sB3, iB3);
                ins3(vB6, cbase + n1 + 8, sB1, iB1, sB2, iB2, sB3, iB3);
                ins3(vB7, cbase + n1 + 9, sB1, iB1, sB2, iB2, sB3, iB3);
            }
        }
    }

    // ---- merge top-3 across the quad ----
    #pragma unroll
    for (int d = 1; d <= 2; d <<= 1) {
        float t1 = __shfl_xor_sync(~0u, sA1, d); int j1 = __shfl_xor_sync(~0u, iA1, d);
        float t2 = __shfl_xor_sync(~0u, sA2, d); int j2 = __shfl_xor_sync(~0u, iA2, d);
        float t3 = __shfl_xor_sync(~0u, sA3, d); int j3 = __shfl_xor_sync(~0u, iA3, d);
        ins3(t1, j1, sA1, iA1, sA2, iA2, sA3, iA3);
        ins3(t2, j2, sA1, iA1, sA2, iA2, sA3, iA3);
        ins3(t3, j3, sA1, iA1, sA2, iA2, sA3, iA3);
        t1 = __shfl_xor_sync(~0u, sB1, d); j1 = __shfl_xor_sync(~0u, iB1, d);
        t2 = __shfl_xor_sync(~0u, sB2, d); j2 = __shfl_xor_sync(~0u, iB2, d);
        t3 = __shfl_xor_sync(~0u, sB3, d); j3 = __shfl_xor_sync(~0u, iB3, d);
        ins3(t1, j1, sB1, iB1, sB2, iB2, sB3, iB3);
        ins3(t2, j2, sB1, iB1, sB2, iB2, sB3, iB3);
        ins3(t3, j3, sB1, iB1, sB2, iB2, sB3, iB3);
    }
    if ((l & 3) == 0) {
        int rA = w * 16 + (l >> 2);
        s_ts[rA * 3 + 0] = sA1; s_ts[rA * 3 + 1] = sA2; s_ts[rA * 3 + 2] = sA3;
        s_ti[rA * 3 + 0] = iA1; s_ti[rA * 3 + 1] = iA2; s_ti[rA * 3 + 2] = iA3;
        int rB = rA + 8;
        s_ts[rB * 3 + 0] = sB1; s_ts[rB * 3 + 1] = sB2; s_ts[rB * 3 + 2] = sB3;
        s_ti[rB * 3 + 0] = iB1; s_ti[rB * 3 + 1] = iB2; s_ti[rB * 3 + 2] = iB3;
    }
    __syncthreads();

    // ---- per-row certification + rescue + outputs (threads 0..127) ----
    float err = 0.0f;
    if (tid < ROWS_PER_CTA) {
        int row = row0 + tid;
        const float4* x4 = (const float4*)(inp + (size_t)row * D);
        float xs = 0.0f;
        #pragma unroll
        for (int i = 0; i < 16; i++) {
            float4 v = x4[i];
            xs += v.x * v.x + v.y * v.y + v.z * v.z + v.w * v.w;
        }
        // score-domain certification margin: 4*(||x||*max||cl|| + slack)
        float margin = 4.0f * (sqrtf(xs) * sqrtf(g_maxcl2) + 1e-3f);

        float s1 = s_ts[tid * 3], s2 = s_ts[tid * 3 + 1], s3 = s_ts[tid * 3 + 2];
        int i1 = s_ti[tid * 3], i2 = s_ti[tid * 3 + 1], i3 = s_ti[tid * 3 + 2];
        int bidx;
        if (s3 < s1 + margin) {
            // cannot certify winner is in top-3: full exact scan (rare)
            float best = 3.4e38f; bidx = 0;
            for (int j = 0; j < KCODES; j++) {
                float e = exact_score(x4, codebook, j);
                if (e < best) { best = e; bidx = j; }
            }
        } else if (s2 < s1 + margin) {
            float e1 = exact_score(x4, codebook, i1);
            float e2 = exact_score(x4, codebook, i2);
            float eb = e1; bidx = i1;
            if (e2 < eb || (e2 == eb && i2 < bidx)) { eb = e2; bidx = i2; }
            float e3 = exact_score(x4, codebook, i3);
            if (e3 < eb || (e3 == eb && i3 < bidx)) { eb = e3; bidx = i3; }
        } else {
            bidx = i1;
        }

        float q[D];
        const float4* q4 = (const float4*)(codebook + (size_t)bidx * D);
        #pragma unroll
        for (int i = 0; i < 16; i++) {
            float4 qq = q4[i];
            float4 x = x4[i];
            q[4 * i + 0] = qq.x; q[4 * i + 1] = qq.y;
            q[4 * i + 2] = qq.z; q[4 * i + 3] = qq.w;
            float dx = x.x - qq.x, dy = x.y - qq.y;
            float dz = x.z - qq.z, dw = x.w - qq.w;
            err += dx * dx + dy * dy + dz * dz + dw * dw;
        }
        // z_q at out+1 (4B offset): i=0,1,2,63 scalar; i=3..62 aligned float4
        float* orow = out + 1 + (size_t)row * D;
        orow[0] = q[0]; orow[1] = q[1]; orow[2] = q[2];
        #pragma unroll
        for (int b = 0; b < 15; b++) {
            int i = 3 + 4 * b;
            *(float4*)(orow + i) = make_float4(q[i], q[i + 1], q[i + 2], q[i + 3]);
        }
        orow[63] = q[63];
        out[1 + (size_t)n_rows * D + row] = (float)bidx;
    }
    #pragma unroll
    for (int off = 16; off > 0; off >>= 1)
        err += __shfl_down_sync(0xffffffffu, err, off);
    if ((tid & 31) == 0 && err != 0.0f)
        atomicAdd(&g_loss_accum, (double)err);

    // ---- last CTA finalizes loss ----
    __syncthreads();
    if (tid == 0) {
        __threadfence();
        unsigned tkt = atomicAdd(&g_ticket, 1u);
        if (tkt == gridDim.x - 1) {
            __threadfence();
            double L = g_loss_accum;
            out[0] = (float)(L * (1.25 / ((double)n_rows * (double)D)));
            g_loss_accum = 0.0;
            g_ticket = 0u;
        }
    }
}

extern "C" void kernel_launch(void* const* d_in, const int* in_sizes, int n_in,
                              void* d_out, int out_size) {
    const float* inp = (const float*)d_in[0];
    const float* codebook = (const float*)d_in[1];
    float* out = (float*)d_out;
    const int n_rows = in_sizes[0] / D;   // 131072

    static bool attr_done = false;
    if (!attr_done) {
        cudaFuncSetAttribute(vq_main_kernel,
                             cudaFuncAttributeMaxDynamicSharedMemorySize,
                             SMEM_TOTAL);
        attr_done = true;
    }
    vq_prep_kernel<<<(KCODES + 255) / 256, 256>>>(codebook);
    vq_main_kernel<<<n_rows / ROWS_PER_CTA, TPB, SMEM_TOTAL>>>(inp, codebook,
                                                               out, n_rows);
    (void)n_in; (void)out_size;
}

// round 10
// speedup vs baseline: 1.9894x; 1.9894x over previous
#include <cuda_runtime.h>
#include <cuda_fp16.h>
#include <cstdint>

// QuantizedCodebook: inputs [32,4096,64] f32, codebook [1024,64] f32.
// Output (f32 concat): [ loss(1) | z_q(N*64) | indices-as-f32(N) ]
//
// R10: 3-plane-cross fp16 HMMA: dot ~= xh*ch + xl*ch + xh*cl.
// Error = (r-xl)*ch + r*cl + xh*rho, bounded by exact per-codebook maxima
// (maxcl2, maxrho2, maxc2 from prep) => margin ~2.5e-4. Top-4 + exact
// rescore; full exact scan only if top-4 uncertifiable (P ~ 1e-9).
// 6 independent MMA chains per 16-code block (3 banks x 2 positions).

#define D 64
#define KCODES 1024
#define TPB 256
#define ROWS_PER_CTA 128
#define CHUNK_N 64
#define NCHUNKS (KCODES / CHUNK_N)       // 16
#define NK 4                              // K=64 -> 4 k16 steps
#define RSA 272                           // A row: 128 fp16 (hi|lo) + 16B pad
#define RSB 272                           // B row: 128 fp16 (ch|cl) + 16B pad

// dynamic smem layout (A-stage overlaps the two B buffers exactly)
#define SM_B0 0                           // 64*272 = 17408
#define SM_B1 17408
#define SM_CS 34816                       // csqr[1024] (4096)
#define SM_TS 38912                       // float top4 s [128][4] (2048)
#define SM_TI 40960                       // int   top4 i [128][4] (2048)
#define SMEM_TOTAL 43008

__device__ double g_loss_accum;
__device__ unsigned int g_ticket;
__device__ float g_maxcl2 = 0.0f;         // max ||cl||^2
__device__ float g_maxrho2 = 0.0f;        // max ||c - ch - cl||^2
__device__ float g_maxc2 = 0.0f;          // max ||c||^2
__device__ float g_csqr[KCODES];
__device__ unsigned int g_cb16[KCODES * 64];  // per code: [ch 32 u32 | cl 32 u32]

// ---------------- helpers ----------------
__device__ __forceinline__ uint32_t smem_u32(const void* p) {
    uint32_t a;
    asm("{ .reg .u64 t; cvta.to.shared.u64 t, %1; cvt.u32.u64 %0, t; }"
        : "=r"(a) : "l"(p));
    return a;
}
__device__ __forceinline__ uint32_t packh(float a, float b) {   // lo=a, hi=b
    uint32_t r;
    asm("cvt.rn.f16x2.f32 %0, %1, %2;" : "=r"(r) : "f"(b), "f"(a));
    return r;
}
__device__ __forceinline__ float2 unph(uint32_t h) {
    __half2 hh = *reinterpret_cast<__half2*>(&h);
    return __half22float2(hh);
}
__device__ __forceinline__ void ldsm4(uint32_t& r0, uint32_t& r1,
                                      uint32_t& r2, uint32_t& r3, uint32_t a) {
    asm volatile("ldmatrix.sync.aligned.m8n8.x4.shared.b16 {%0,%1,%2,%3}, [%4];"
                 : "=r"(r0), "=r"(r1), "=r"(r2), "=r"(r3) : "r"(a));
}
__device__ __forceinline__ void mma16816(float& c0, float& c1, float& c2, float& c3,
                                         uint32_t a0, uint32_t a1, uint32_t a2,
                                         uint32_t a3, uint32_t b0, uint32_t b1) {
    asm("mma.sync.aligned.m16n8k16.row.col.f32.f16.f16.f32 "
        "{%0,%1,%2,%3}, {%4,%5,%6,%7}, {%8,%9}, {%0,%1,%2,%3};"
        : "+f"(c0), "+f"(c1), "+f"(c2), "+f"(c3)
        : "r"(a0), "r"(a1), "r"(a2), "r"(a3), "r"(b0), "r"(b1));
}
__device__ __forceinline__ void cpa16(uint32_t dst, const void* src) {
    asm volatile("cp.async.cg.shared.global [%0], [%1], 16;"
                 :: "r"(dst), "l"(src));
}
#define CP_COMMIT() asm volatile("cp.async.commit_group;" ::: "memory")
#define CP_WAIT0()  asm volatile("cp.async.wait_group 0;" ::: "memory")

__device__ __forceinline__ void ins4(float s, int idx,
                                     float& s1, int& i1, float& s2, int& i2,
                                     float& s3, int& i3, float& s4, int& i4) {
    if (s < s4) {
        if (s < s3) {
            if (s < s2) {
                if (s < s1) {
                    s4 = s3; i4 = i3; s3 = s2; i3 = i2;
                    s2 = s1; i2 = i1; s1 = s; i1 = idx;
                } else { s4 = s3; i4 = i3; s3 = s2; i3 = i2; s2 = s; i2 = idx; }
            } else { s4 = s3; i4 = i3; s3 = s; i3 = idx; }
        } else { s4 = s; i4 = idx; }
    }
}

// ---------------- kernel 1: prep ----------------
__global__ void vq_prep_kernel(const float* __restrict__ codebook) {
    int j = blockIdx.x * blockDim.x + threadIdx.x;
    if (j == 0) { g_loss_accum = 0.0; g_ticket = 0u; }
    if (j >= KCODES) return;
    const float4* c4 = (const float4*)(codebook + (size_t)j * D);
    unsigned int* q = g_cb16 + (size_t)j * 64;
    float s = 0.0f, cl2 = 0.0f, rho2 = 0.0f;
    #pragma unroll
    for (int i = 0; i < 16; i++) {
        float4 v = c4[i];
        s += v.x * v.x + v.y * v.y + v.z * v.z + v.w * v.w;
        uint32_t h0 = packh(v.x, v.y), h1 = packh(v.z, v.w);
        float2 f0 = unph(h0), f1 = unph(h1);
        float r0 = v.x - f0.x, r1 = v.y - f0.y;
        float r2 = v.z - f1.x, r3 = v.w - f1.y;
        uint32_t l0 = packh(r0, r1), l1 = packh(r2, r3);
        float2 g0 = unph(l0), g1 = unph(l1);
        float p0 = r0 - g0.x, p1 = r1 - g0.y, p2 = r2 - g1.x, p3 = r3 - g1.y;
        cl2  += g0.x * g0.x + g0.y * g0.y + g1.x * g1.x + g1.y * g1.y;
        rho2 += p0 * p0 + p1 * p1 + p2 * p2 + p3 * p3;
        q[2 * i] = h0;      q[2 * i + 1] = h1;         // ch plane
        q[32 + 2 * i] = l0; q[32 + 2 * i + 1] = l1;    // cl plane
    }
    g_csqr[j] = s;
    atomicMax((int*)&g_maxcl2, __float_as_int(cl2));
    atomicMax((int*)&g_maxrho2, __float_as_int(rho2));
    atomicMax((int*)&g_maxc2, __float_as_int(s));
}

__device__ __forceinline__ float exact_score(const float4* x4,
                                             const float* __restrict__ cb, int j) {
    const float4* c4 = (const float4*)(cb + (size_t)j * D);
    float dot = 0.0f;
    #pragma unroll
    for (int i = 0; i < 16; i++) {
        float4 a = x4[i], b = c4[i];
        dot += a.x * b.x + a.y * b.y + a.z * b.z + a.w * b.w;
    }
    return fmaf(-2.0f, dot, g_csqr[j]);
}

// ---------------- kernel 2: main ----------------
__global__ void __launch_bounds__(TPB, 2)
vq_main_kernel(const float* __restrict__ inp,
               const float* __restrict__ codebook,
               float* __restrict__ out, int n_rows) {
    extern __shared__ char dsm[];
    const uint32_t sbase = smem_u32(dsm);
    float* s_csqr = (float*)(dsm + SM_CS);
    float* s_ts = (float*)(dsm + SM_TS);
    int*   s_ti = (int*)(dsm + SM_TI);

    const int tid = threadIdx.x;
    const int l = tid & 31;
    const int w = tid >> 5;
    const int row0 = blockIdx.x * ROWS_PER_CTA;

    // ---- stage A [128 rows][xh(64)|xl(64)] fp16, stride 272 ----
    if (tid < ROWS_PER_CTA) {
        const float4* xr = (const float4*)(inp + (size_t)(row0 + tid) * D);
        uint32_t* arow = (uint32_t*)(dsm + tid * RSA);
        #pragma unroll
        for (int i = 0; i < 16; i++) {
            float4 v = xr[i];
            uint32_t h0 = packh(v.x, v.y), h1 = packh(v.z, v.w);
            float2 f0 = unph(h0), f1 = unph(h1);
            uint32_t l0 = packh(v.x - f0.x, v.y - f0.y);
            uint32_t l1 = packh(v.z - f1.x, v.w - f1.y);
            arow[2 * i] = h0;       arow[2 * i + 1] = h1;
            arow[32 + 2 * i] = l0;  arow[32 + 2 * i + 1] = l1;
        }
    }
    for (int g = tid; g < KCODES; g += TPB) s_csqr[g] = g_csqr[g];
    __syncthreads();

    // ---- preload A fragments (held all kernel) ----
    uint32_t afh[NK][4], afl[NK][4];
    {
        uint32_t aoff = (uint32_t)((w * 16 + (l & 15)) * RSA + ((l & 16) ? 16 : 0));
        #pragma unroll
        for (int k = 0; k < NK; k++) {
            ldsm4(afh[k][0], afh[k][1], afh[k][2], afh[k][3], sbase + aoff + k * 32);
            ldsm4(afl[k][0], afl[k][1], afl[k][2], afl[k][3], sbase + aoff + 128 + k * 32);
        }
    }
    __syncthreads();   // all A reads done before B overwrites the region

    float sA1 = 3.4e38f, sA2 = 3.4e38f, sA3 = 3.4e38f, sA4 = 3.4e38f;
    float sB1 = 3.4e38f, sB2 = 3.4e38f, sB3 = 3.4e38f, sB4 = 3.4e38f;
    int iA1 = 0, iA2 = 0, iA3 = 0, iA4 = 0;
    int iB1 = 0, iB2 = 0, iB3 = 0, iB4 = 0;

    const uint32_t boff = (uint32_t)(((l & 7) + ((l & 16) ? 8 : 0)) * RSB
                                     + ((l & 8) ? 16 : 0));
    const int q2 = 2 * (l & 3);
    const uint4* cb4 = (const uint4*)g_cb16;
    const uint32_t bb[2] = { sbase + SM_B0, sbase + SM_B1 };

    // prefetch chunk 0: 64 codes x 256B = 1024 x 16B
    #pragma unroll
    for (int g = tid; g < CHUNK_N * 16; g += TPB) {
        int r = g >> 4, c = g & 15;
        cpa16(bb[0] + (uint32_t)(r * RSB + c * 16), cb4 + (size_t)r * 16 + c);
    }
    CP_COMMIT();

    for (int t = 0; t < NCHUNKS; t++) {
        CP_WAIT0();
        __syncthreads();
        if (t + 1 < NCHUNKS) {
            const uint4* src = cb4 + (size_t)(t + 1) * CHUNK_N * 16;
            uint32_t dstb = bb[(t + 1) & 1];
            #pragma unroll
            for (int g = tid; g < CHUNK_N * 16; g += TPB) {
                int r = g >> 4, c = g & 15;
                cpa16(dstb + (uint32_t)(r * RSB + c * 16), src + (size_t)r * 16 + c);
            }
            CP_COMMIT();
        }
        const uint32_t bch = bb[t & 1];

        #pragma unroll
        for (int blk = 0; blk < 4; blk++) {   // 16 codes per block
            // 3 banks x 2 positions = 6 independent HMMA chains, depth 4
            float hh0 = 0.f, hh1 = 0.f, hh2 = 0.f, hh3 = 0.f;
            float hh4 = 0.f, hh5 = 0.f, hh6 = 0.f, hh7 = 0.f;
            float lh0 = 0.f, lh1 = 0.f, lh2 = 0.f, lh3 = 0.f;
            float lh4 = 0.f, lh5 = 0.f, lh6 = 0.f, lh7 = 0.f;
            float hl0 = 0.f, hl1 = 0.f, hl2 = 0.f, hl3 = 0.f;
            float hl4 = 0.f, hl5 = 0.f, hl6 = 0.f, hl7 = 0.f;
            uint32_t bc = bch + (uint32_t)(blk * 16 * RSB) + boff;
            #pragma unroll
            for (int k = 0; k < NK; k++) {
                uint32_t c0, c1, c2, c3, d0, d1, d2, d3;
                ldsm4(c0, c1, c2, c3, bc + k * 32);          // ch frags
                ldsm4(d0, d1, d2, d3, bc + 128 + k * 32);    // cl frags
                mma16816(hh0, hh1, hh2, hh3, afh[k][0], afh[k][1], afh[k][2], afh[k][3], c0, c1);
                mma16816(hh4, hh5, hh6, hh7, afh[k][0], afh[k][1], afh[k][2], afh[k][3], c2, c3);
                mma16816(lh0, lh1, lh2, lh3, afl[k][0], afl[k][1], afl[k][2], afl[k][3], c0, c1);
                mma16816(lh4, lh5, lh6, lh7, afl[k][0], afl[k][1], afl[k][2], afl[k][3], c2, c3);
                mma16816(hl0, hl1, hl2, hl3, afh[k][0], afh[k][1], afh[k][2], afh[k][3], d0, d1);
                mma16816(hl4, hl5, hl6, hl7, afh[k][0], afh[k][1], afh[k][2], afh[k][3], d2, d3);
            }
            int cbase = t * CHUNK_N + blk * 16;
            int n0 = cbase + q2;        // pos0 cols
            int n1 = n0 + 8;            // pos1 cols
            float cs0 = s_csqr[n0], cs1 = s_csqr[n0 + 1];
            float cs2 = s_csqr[n1], cs3 = s_csqr[n1 + 1];

            float vA0 = fmaf(-2.f, hh0 + lh0 + hl0, cs0);
            float vA1 = fmaf(-2.f, hh1 + lh1 + hl1, cs1);
            float vA2 = fmaf(-2.f, hh4 + lh4 + hl4, cs2);
            float vA3 = fmaf(-2.f, hh5 + lh5 + hl5, cs3);
            float vB0 = fmaf(-2.f, hh2 + lh2 + hl2, cs0);
            float vB1 = fmaf(-2.f, hh3 + lh3 + hl3, cs1);
            float vB2 = fmaf(-2.f, hh6 + lh6 + hl6, cs2);
            float vB3 = fmaf(-2.f, hh7 + lh7 + hl7, cs3);

            float mA = fminf(fminf(vA0, vA1), fminf(vA2, vA3));
            float mB = fminf(fminf(vB0, vB1), fminf(vB2, vB3));
            if (mA < sA4) {
                ins4(vA0, n0,     sA1, iA1, sA2, iA2, sA3, iA3, sA4, iA4);
                ins4(vA1, n0 + 1, sA1, iA1, sA2, iA2, sA3, iA3, sA4, iA4);
                ins4(vA2, n1,     sA1, iA1, sA2, iA2, sA3, iA3, sA4, iA4);
                ins4(vA3, n1 + 1, sA1, iA1, sA2, iA2, sA3, iA3, sA4, iA4);
            }
            if (mB < sB4) {
                ins4(vB0, n0,     sB1, iB1, sB2, iB2, sB3, iB3, sB4, iB4);
                ins4(vB1, n0 + 1, sB1, iB1, sB2, iB2, sB3, iB3, sB4, iB4);
                ins4(vB2, n1,     sB1, iB1, sB2, iB2, sB3, iB3, sB4, iB4);
                ins4(vB3, n1 + 1, sB1, iB1, sB2, iB2, sB3, iB3, sB4, iB4);
            }
        }
    }

    // ---- merge top-4 across the quad ----
    #pragma unroll
    for (int d = 1; d <= 2; d <<= 1) {
        float t1 = __shfl_xor_sync(~0u, sA1, d); int j1 = __shfl_xor_sync(~0u, iA1, d);
        float t2 = __shfl_xor_sync(~0u, sA2, d); int j2 = __shfl_xor_sync(~0u, iA2, d);
        float t3 = __shfl_xor_sync(~0u, sA3, d); int j3 = __shfl_xor_sync(~0u, iA3, d);
        float t4 = __shfl_xor_sync(~0u, sA4, d); int j4 = __shfl_xor_sync(~0u, iA4, d);
        ins4(t1, j1, sA1, iA1, sA2, iA2, sA3, iA3, sA4, iA4);
        ins4(t2, j2, sA1, iA1, sA2, iA2, sA3, iA3, sA4, iA4);
        ins4(t3, j3, sA1, iA1, sA2, iA2, sA3, iA3, sA4, iA4);
        ins4(t4, j4, sA1, iA1, sA2, iA2, sA3, iA3, sA4, iA4);
        t1 = __shfl_xor_sync(~0u, sB1, d); j1 = __shfl_xor_sync(~0u, iB1, d);
        t2 = __shfl_xor_sync(~0u, sB2, d); j2 = __shfl_xor_sync(~0u, iB2, d);
        t3 = __shfl_xor_sync(~0u, sB3, d); j3 = __shfl_xor_sync(~0u, iB3, d);
        t4 = __shfl_xor_sync(~0u, sB4, d); j4 = __shfl_xor_sync(~0u, iB4, d);
        ins4(t1, j1, sB1, iB1, sB2, iB2, sB3, iB3, sB4, iB4);
        ins4(t2, j2, sB1, iB1, sB2, iB2, sB3, iB3, sB4, iB4);
        ins4(t3, j3, sB1, iB1, sB2, iB2, sB3, iB3, sB4, iB4);
        ins4(t4, j4, sB1, iB1, sB2, iB2, sB3, iB3, sB4, iB4);
    }
    if ((l & 3) == 0) {
        int rA = w * 16 + (l >> 2);
        s_ts[rA * 4 + 0] = sA1; s_ts[rA * 4 + 1] = sA2;
        s_ts[rA * 4 + 2] = sA3; s_ts[rA * 4 + 3] = sA4;
        s_ti[rA * 4 + 0] = iA1; s_ti[rA * 4 + 1] = iA2;
        s_ti[rA * 4 + 2] = iA3; s_ti[rA * 4 + 3] = iA4;
        int rB = rA + 8;
        s_ts[rB * 4 + 0] = sB1; s_ts[rB * 4 + 1] = sB2;
        s_ts[rB * 4 + 2] = sB3; s_ts[rB * 4 + 3] = sB4;
        s_ti[rB * 4 + 0] = iB1; s_ti[rB * 4 + 1] = iB2;
        s_ti[rB * 4 + 2] = iB3; s_ti[rB * 4 + 3] = iB4;
    }
    __syncthreads();

    // ---- per-row certification + rescue + outputs (threads 0..127) ----
    float err = 0.0f;
    if (tid < ROWS_PER_CTA) {
        int row = row0 + tid;
        const float4* x4 = (const float4*)(inp + (size_t)row * D);
        float xs = 0.0f, xl2 = 0.0f;
        #pragma unroll
        for (int i = 0; i < 16; i++) {
            float4 v = x4[i];
            xs += v.x * v.x + v.y * v.y + v.z * v.z + v.w * v.w;
            uint32_t h0 = packh(v.x, v.y), h1 = packh(v.z, v.w);
            float2 f0 = unph(h0), f1 = unph(h1);
            float r0 = v.x - f0.x, r1 = v.y - f0.y;
            float r2 = v.z - f1.x, r3 = v.w - f1.y;
            xl2 += r0 * r0 + r1 * r1 + r2 * r2 + r3 * r3;
        }
        // rigorous 2*|approx - exact| bound:
        //  err <= ||r||*maxcl + ||x||*maxrho + ||r||*2^-11*maxc + fp32 slack
        float xln = sqrtf(xl2), xn = sqrtf(xs);
        float margin = 2.0f * (xln * (sqrtf(g_maxcl2) + 6e-4f * sqrtf(g_maxc2))
                               + xn * sqrtf(g_maxrho2) + 1e-4f);

        float s1 = s_ts[tid * 4], s2 = s_ts[tid * 4 + 1];
        float s4 = s_ts[tid * 4 + 3];
        int i1 = s_ti[tid * 4], i2 = s_ti[tid * 4 + 1];
        int i3 = s_ti[tid * 4 + 2], i4 = s_ti[tid * 4 + 3];
        int bidx;
        if (s4 - s1 <= margin) {
            // cannot certify winner in top-4: full exact scan (P ~ 1e-9)
            float best = 3.4e38f; bidx = 0;
            for (int j = 0; j < KCODES; j += 2) {
                float e0 = exact_score(x4, codebook, j);
                float e1 = exact_score(x4, codebook, j + 1);
                if (e0 < best) { best = e0; bidx = j; }
                if (e1 < best) { best = e1; bidx = j + 1; }
            }
        } else if (s2 - s1 <= margin) {
            float e1 = exact_score(x4, codebook, i1);
            float e2 = exact_score(x4, codebook, i2);
            float e3 = exact_score(x4, codebook, i3);
            float e4 = exact_score(x4, codebook, i4);
            float eb = e1; bidx = i1;
            if (e2 < eb || (e2 == eb && i2 < bidx)) { eb = e2; bidx = i2; }
            if (e3 < eb || (e3 == eb && i3 < bidx)) { eb = e3; bidx = i3; }
            if (e4 < eb || (e4 == eb && i4 < bidx)) { eb = e4; bidx = i4; }
        } else {
            bidx = i1;
        }

        float q[D];
        const float4* q4 = (const float4*)(codebook + (size_t)bidx * D);
        #pragma unroll
        for (int i = 0; i < 16; i++) {
            float4 qq = q4[i];
            float4 x = x4[i];
            q[4 * i + 0] = qq.x; q[4 * i + 1] = qq.y;
            q[4 * i + 2] = qq.z; q[4 * i + 3] = qq.w;
            float dx = x.x - qq.x, dy = x.y - qq.y;
            float dz = x.z - qq.z, dw = x.w - qq.w;
            err += dx * dx + dy * dy + dz * dz + dw * dw;
        }
        // z_q at out+1 (4B offset): i=0,1,2,63 scalar; i=3..62 aligned float4
        float* orow = out + 1 + (size_t)row * D;
        orow[0] = q[0]; orow[1] = q[1]; orow[2] = q[2];
        #pragma unroll
        for (int b = 0; b < 15; b++) {
            int i = 3 + 4 * b;
            *(float4*)(orow + i) = make_float4(q[i], q[i + 1], q[i + 2], q[i + 3]);
        }
        orow[63] = q[63];
        out[1 + (size_t)n_rows * D + row] = (float)bidx;
    }
    #pragma unroll
    for (int off = 16; off > 0; off >>= 1)
        err += __shfl_down_sync(0xffffffffu, err, off);
    if ((tid & 31) == 0 && err != 0.0f)
        atomicAdd(&g_loss_accum, (double)err);

    // ---- last CTA finalizes loss ----
    __syncthreads();
    if (tid == 0) {
        __threadfence();
        unsigned tkt = atomicAdd(&g_ticket, 1u);
        if (tkt == gridDim.x - 1) {
            __threadfence();
            double L = g_loss_accum;
            out[0] = (float)(L * (1.25 / ((double)n_rows * (double)D)));
            g_loss_accum = 0.0;
            g_ticket = 0u;
        }
    }
}

extern "C" void kernel_launch(void* const* d_in, const int* in_sizes, int n_in,
                              void* d_out, int out_size) {
    const float* inp = (const float*)d_in[0];
    const float* codebook = (const float*)d_in[1];
    float* out = (float*)d_out;
    const int n_rows = in_sizes[0] / D;   // 131072

    static bool attr_done = false;
    if (!attr_done) {
        cudaFuncSetAttribute(vq_main_kernel,
                             cudaFuncAttributeMaxDynamicSharedMemorySize,
                             SMEM_TOTAL);
        attr_done = true;
    }
    vq_prep_kernel<<<(KCODES + 255) / 256, 256>>>(codebook);
    vq_main_kernel<<<n_rows / ROWS_PER_CTA, TPB, SMEM_TOTAL>>>(inp, codebook,
                                                               out, n_rows);
    (void)n_in; (void)out_size;
}